// round 3
// baseline (speedup 1.0000x reference)
#include <cuda_runtime.h>
#include <math.h>

// Problem constants
#define EG 1024      // embed dim
#define MG 2048      // B*S rows
#define SG 1024      // seq len
#define HG 16        // heads
#define DH 64        // head dim

// ---------------- scratch (device globals: no runtime allocation allowed) ----
__device__ float g_qa[MG * EG];
__device__ float g_qb[MG * EG];
__device__ float g_ka[MG * EG];
__device__ float g_kb[MG * EG];
__device__ float g_va[MG * EG];
__device__ float g_vb[MG * EG];
__device__ float g_oa[MG * EG];
__device__ float g_ob[MG * EG];

// ---------------------------------------------------------------------------
// Fused quaternion-complex dense:
//   outA[m,n] = sum_k xa[m,k]*wa[n,k] + j2 * sum_k xb[m,k]*wb[n,k] + ba[n]
//   outB[m,n] = sum_k xa[m,k]*wb[n,k] +      sum_k xb[m,k]*wa[n,k] + bb[n]
// Both X and W are row-major with K contiguous (NT GEMM). 64x64 block tile,
// 256 threads, 4x4 per-thread micro-tile, two accumulators per output elem.
// ---------------------------------------------------------------------------
__global__ __launch_bounds__(256) void qc_gemm_kernel(
    const float* __restrict__ xa, const float* __restrict__ xb,
    const float* __restrict__ wa, const float* __restrict__ wb,
    const float* __restrict__ ba, const float* __restrict__ bb,
    const float* __restrict__ theta_ptr,
    float* __restrict__ outA, float* __restrict__ outB)
{
    __shared__ float sXa[16][64];
    __shared__ float sXb[16][64];
    __shared__ float sWa[16][64];
    __shared__ float sWb[16][64];

    const int tid = threadIdx.x;
    const int tx = tid & 15;        // output-col group
    const int ty = tid >> 4;        // output-row group
    const int m0 = blockIdx.y * 64;
    const int n0 = blockIdx.x * 64;

    const float j2 = sinf(2.0f * theta_ptr[0]) - 1.0f;

    // loader mapping: 256 threads * float4 = 1024 floats = one 64x16 tile
    const int lrow = tid >> 2;          // 0..63
    const int lk   = (tid & 3) << 2;    // 0,4,8,12

    float accA[4][4] = {};
    float accB[4][4] = {};

    for (int k0 = 0; k0 < EG; k0 += 16) {
        float4 vxa = *(const float4*)&xa[(m0 + lrow) * EG + k0 + lk];
        float4 vxb = *(const float4*)&xb[(m0 + lrow) * EG + k0 + lk];
        float4 vwa = *(const float4*)&wa[(n0 + lrow) * EG + k0 + lk];
        float4 vwb = *(const float4*)&wb[(n0 + lrow) * EG + k0 + lk];

        __syncthreads();   // previous iteration's compute done before overwrite

        sXa[lk + 0][lrow] = vxa.x; sXa[lk + 1][lrow] = vxa.y;
        sXa[lk + 2][lrow] = vxa.z; sXa[lk + 3][lrow] = vxa.w;
        sXb[lk + 0][lrow] = vxb.x; sXb[lk + 1][lrow] = vxb.y;
        sXb[lk + 2][lrow] = vxb.z; sXb[lk + 3][lrow] = vxb.w;
        sWa[lk + 0][lrow] = vwa.x; sWa[lk + 1][lrow] = vwa.y;
        sWa[lk + 2][lrow] = vwa.z; sWa[lk + 3][lrow] = vwa.w;
        sWb[lk + 0][lrow] = vwb.x; sWb[lk + 1][lrow] = vwb.y;
        sWb[lk + 2][lrow] = vwb.z; sWb[lk + 3][lrow] = vwb.w;

        __syncthreads();

        #pragma unroll
        for (int kk = 0; kk < 16; kk++) {
            float4 fxa = *(const float4*)&sXa[kk][ty * 4];
            float4 fxb = *(const float4*)&sXb[kk][ty * 4];
            float4 fwa = *(const float4*)&sWa[kk][tx * 4];
            float4 fwb = *(const float4*)&sWb[kk][tx * 4];

            float xaf[4] = {fxa.x, fxa.y, fxa.z, fxa.w};
            float xbf[4] = {fxb.x, fxb.y, fxb.z, fxb.w};
            float waf[4] = {fwa.x, fwa.y, fwa.z, fwa.w};
            float wbf[4] = {fwb.x, fwb.y, fwb.z, fwb.w};
            float xbj[4];
            #pragma unroll
            for (int i = 0; i < 4; i++) xbj[i] = j2 * xbf[i];

            #pragma unroll
            for (int i = 0; i < 4; i++) {
                #pragma unroll
                for (int j = 0; j < 4; j++) {
                    accA[i][j] += xaf[i] * waf[j] + xbj[i] * wbf[j];
                    accB[i][j] += xaf[i] * wbf[j] + xbf[i] * waf[j];
                }
            }
        }
    }

    #pragma unroll
    for (int i = 0; i < 4; i++) {
        const int m = m0 + ty * 4 + i;
        #pragma unroll
        for (int j = 0; j < 4; j++) {
            const int n = n0 + tx * 4 + j;
            outA[m * EG + n] = accA[i][j] + ba[n];
            outB[m * EG + n] = accB[i][j] + bb[n];
        }
    }
}

// ---------------------------------------------------------------------------
// RoPE applied in place to g_qa, g_qb, g_ka, g_kb.
// Per (row, h, i<32): pair (d=h*64+i, d+32) rotated by ang = s * 10000^(-i/32).
// ---------------------------------------------------------------------------
__global__ __launch_bounds__(256) void rope_kernel()
{
    const int PAIRS = MG * (EG / 2);          // per tensor: 2048 * 512
    int t = blockIdx.x * blockDim.x + threadIdx.x;
    if (t >= 4 * PAIRS) return;

    const int w = t / PAIRS;
    const int p = t % PAIRS;
    float* X = (w == 0) ? g_qa : (w == 1) ? g_qb : (w == 2) ? g_ka : g_kb;

    const int row = p >> 9;          // / 512
    const int pp  = p & 511;
    const int h   = pp >> 5;
    const int i   = pp & 31;
    const int s   = row & (SG - 1);  // row % S

    const float freq = (float)exp((double)(-i) * (1.0 / 32.0) * log(10000.0));
    float sn, cs;
    sincosf((float)s * freq, &sn, &cs);

    const int base = row * EG + h * DH + i;
    const float x1 = X[base];
    const float x2 = X[base + 32];
    X[base]      = x1 * cs - x2 * sn;
    X[base + 32] = x2 * cs + x1 * sn;
}

// ---------------------------------------------------------------------------
// Flash-style complex-magnitude attention.
//   s_a = qa.ka + j2h * qb.kb ;  s_b = qa.kb + qb.ka
//   mag = sqrt(s_a^2 + s_b^2 + 1e-8)/8, causal mask -> -1e9, online softmax,
//   out_a = P@va, out_b = P@vb.
// Grid (S/32, H, B), 256 threads. Per thread: 1 q-row, 4 score cols (c*4+jj),
// 8 output dims (c*8+dd).
// ---------------------------------------------------------------------------
__global__ __launch_bounds__(256) void attn_kernel(const float* __restrict__ thetas_head)
{
    __shared__ float sQa[32][65];
    __shared__ float sQb[32][65];
    __shared__ float sKa[32][65];   // reused for Va
    __shared__ float sKb[32][65];   // reused for Vb
    __shared__ float sP [32][33];

    const int b  = blockIdx.z;
    const int h  = blockIdx.y;
    const int r0 = blockIdx.x * 32;
    const int tid = threadIdx.x;
    const int row = tid >> 3;       // 0..31
    const int c   = tid & 7;        // 0..7

    const float j2h = sinf(2.0f * thetas_head[h]) - 1.0f;

    // load Q tile once
    for (int idx = tid; idx < 32 * 64; idx += 256) {
        const int i = idx >> 6, d = idx & 63;
        const int g = (b * SG + r0 + i) * EG + h * DH + d;
        sQa[i][d] = g_qa[g];
        sQb[i][d] = g_qb[g];
    }

    float m = -1e30f, l = 0.0f;
    float acc_a[8] = {};
    float acc_b[8] = {};

    const int ntiles = (r0 >> 5) + 1;   // causal: tiles 0..r0/32
    for (int t = 0; t < ntiles; t++) {
        const int k0 = t * 32;

        __syncthreads();  // Q loaded (t==0) / previous PV reads done
        for (int idx = tid; idx < 32 * 64; idx += 256) {
            const int i = idx >> 6, d = idx & 63;
            const int g = (b * SG + k0 + i) * EG + h * DH + d;
            sKa[i][d] = g_ka[g];
            sKb[i][d] = g_kb[g];
        }
        __syncthreads();

        // scores: 4 columns per thread
        float sa[4] = {}, sb[4] = {};
        for (int d = 0; d < 64; d++) {
            const float qaf = sQa[row][d];
            const float qbf = sQb[row][d];
            const float qbj = j2h * qbf;
            #pragma unroll
            for (int jj = 0; jj < 4; jj++) {
                const int j = c * 4 + jj;
                const float kaf = sKa[j][d];
                const float kbf = sKb[j][d];
                sa[jj] += qaf * kaf + qbj * kbf;
                sb[jj] += qaf * kbf + qbf * kaf;
            }
        }

        float mt = -1e30f;
        float mag[4];
        #pragma unroll
        for (int jj = 0; jj < 4; jj++) {
            const int kidx = k0 + c * 4 + jj;
            if (kidx <= r0 + row) {
                mag[jj] = sqrtf(sa[jj] * sa[jj] + sb[jj] * sb[jj] + 1e-8f) * 0.125f;
            } else {
                mag[jj] = -1e9f;
            }
            mt = fmaxf(mt, mag[jj]);
        }
        #pragma unroll
        for (int o = 1; o < 8; o <<= 1)
            mt = fmaxf(mt, __shfl_xor_sync(0xffffffffu, mt, o));

        const float mnew = fmaxf(m, mt);
        float p[4], psum = 0.0f;
        #pragma unroll
        for (int jj = 0; jj < 4; jj++) {
            p[jj] = expf(mag[jj] - mnew);   // masked -> exp(-1e9-m) == 0
            psum += p[jj];
        }
        #pragma unroll
        for (int o = 1; o < 8; o <<= 1)
            psum += __shfl_xor_sync(0xffffffffu, psum, o);

        const float scale = expf(m - mnew);
        l = l * scale + psum;
        m = mnew;
        #pragma unroll
        for (int dd = 0; dd < 8; dd++) { acc_a[dd] *= scale; acc_b[dd] *= scale; }

        #pragma unroll
        for (int jj = 0; jj < 4; jj++) sP[row][c * 4 + jj] = p[jj];
        __syncthreads();   // P written, K reads done -> safe to overwrite with V

        for (int idx = tid; idx < 32 * 64; idx += 256) {
            const int i = idx >> 6, d = idx & 63;
            const int g = (b * SG + k0 + i) * EG + h * DH + d;
            sKa[i][d] = g_va[g];
            sKb[i][d] = g_vb[g];
        }
        __syncthreads();

        #pragma unroll 4
        for (int j = 0; j < 32; j++) {
            const float pv = sP[row][j];
            #pragma unroll
            for (int dd = 0; dd < 8; dd++) {
                acc_a[dd] += pv * sKa[j][c * 8 + dd];
                acc_b[dd] += pv * sKb[j][c * 8 + dd];
            }
        }
    }

    const float inv_l = 1.0f / l;
    const int g = (b * SG + r0 + row) * EG + h * DH + c * 8;
    #pragma unroll
    for (int dd = 0; dd < 8; dd++) {
        g_oa[g + dd] = acc_a[dd] * inv_l;
        g_ob[g + dd] = acc_b[dd] * inv_l;
    }
}

// ---------------------------------------------------------------------------
extern "C" void kernel_launch(void* const* d_in, const int* in_sizes, int n_in,
                              void* d_out, int out_size)
{
    const float* x_q_a  = (const float*)d_in[0];
    const float* x_q_b  = (const float*)d_in[1];
    const float* x_kv_a = (const float*)d_in[2];
    const float* x_kv_b = (const float*)d_in[3];
    // d_in[4] = mask (causal tril) -- encoded directly in the attention kernel
    const float* layer_theta = (const float*)d_in[5];
    const float* thetas_head = (const float*)d_in[6];
    const float* q_wa = (const float*)d_in[7];
    const float* q_wb = (const float*)d_in[8];
    const float* q_ba = (const float*)d_in[9];
    const float* q_bb = (const float*)d_in[10];
    const float* k_wa = (const float*)d_in[11];
    const float* k_wb = (const float*)d_in[12];
    const float* k_ba = (const float*)d_in[13];
    const float* k_bb = (const float*)d_in[14];
    const float* v_wa = (const float*)d_in[15];
    const float* v_wb = (const float*)d_in[16];
    const float* v_ba = (const float*)d_in[17];
    const float* v_bb = (const float*)d_in[18];
    const float* o_wa = (const float*)d_in[19];
    const float* o_wb = (const float*)d_in[20];
    const float* o_ba = (const float*)d_in[21];
    const float* o_bb = (const float*)d_in[22];

    float *qa, *qb, *ka, *kb, *va, *vb, *oa, *ob;
    cudaGetSymbolAddress((void**)&qa, g_qa);
    cudaGetSymbolAddress((void**)&qb, g_qb);
    cudaGetSymbolAddress((void**)&ka, g_ka);
    cudaGetSymbolAddress((void**)&kb, g_kb);
    cudaGetSymbolAddress((void**)&va, g_va);
    cudaGetSymbolAddress((void**)&vb, g_vb);
    cudaGetSymbolAddress((void**)&oa, g_oa);
    cudaGetSymbolAddress((void**)&ob, g_ob);

    float* outA = (float*)d_out;
    float* outB = (float*)d_out + (size_t)MG * EG;

    const dim3 gg(EG / 64, MG / 64);

    // q / k / v projections
    qc_gemm_kernel<<<gg, 256>>>(x_q_a,  x_q_b,  q_wa, q_wb, q_ba, q_bb, layer_theta, qa, qb);
    qc_gemm_kernel<<<gg, 256>>>(x_kv_a, x_kv_b, k_wa, k_wb, k_ba, k_bb, layer_theta, ka, kb);
    qc_gemm_kernel<<<gg, 256>>>(x_kv_a, x_kv_b, v_wa, v_wb, v_ba, v_bb, layer_theta, va, vb);

    // RoPE on qa,qb,ka,kb (in place)
    rope_kernel<<<(4 * MG * (EG / 2)) / 256, 256>>>();

    // flash complex-magnitude attention -> g_oa, g_ob
    attn_kernel<<<dim3(SG / 32, HG, 2), 256>>>(thetas_head);

    // output projection straight into d_out (out_a then out_b)
    qc_gemm_kernel<<<gg, 256>>>(oa, ob, o_wa, o_wb, o_ba, o_bb, layer_theta, outA, outB);
}

// round 4
// speedup vs baseline: 2.0235x; 2.0235x over previous
#include <cuda_runtime.h>
#include <cuda_bf16.h>
#include <math.h>

// Problem constants
#define EG 1024      // embed dim
#define MG 2048      // B*S rows
#define SG 1024      // seq len
#define HG 16        // heads
#define DH 64        // head dim

// ---------------- scratch (device globals: no runtime allocation allowed) ----
__device__ float g_qa[MG * EG];
__device__ float g_qb[MG * EG];
__device__ float g_ka[MG * EG];
__device__ float g_kb[MG * EG];
__device__ float g_va[MG * EG];
__device__ float g_vb[MG * EG];
__device__ float g_oa[MG * EG];
__device__ float g_ob[MG * EG];

// ---------------------------------------------------------------------------
// bf16 MMA helper: D += A(16x16,row) * B(16x8,col)   fp32 accum
// ---------------------------------------------------------------------------
__device__ __forceinline__ void mma_bf16(float* c, const unsigned* a, const unsigned* b)
{
    asm volatile(
        "mma.sync.aligned.m16n8k16.row.col.f32.bf16.bf16.f32 "
        "{%0,%1,%2,%3}, {%4,%5,%6,%7}, {%8,%9}, {%0,%1,%2,%3};"
        : "+f"(c[0]), "+f"(c[1]), "+f"(c[2]), "+f"(c[3])
        : "r"(a[0]), "r"(a[1]), "r"(a[2]), "r"(a[3]),
          "r"(b[0]), "r"(b[1]));
}

// smem tile strides (bf16 halfword units). BK=32 + pad 8 -> conflict-free frags.
#define TSTR 40

// split fp32 -> bf16 hi/lo, write pairs into smem tiles
__device__ __forceinline__ void split_store4(
    __nv_bfloat16* shi, __nv_bfloat16* slo, int idx, float4 v)
{
    __nv_bfloat16 hx = __float2bfloat16(v.x);
    __nv_bfloat16 hy = __float2bfloat16(v.y);
    __nv_bfloat16 hz = __float2bfloat16(v.z);
    __nv_bfloat16 hw = __float2bfloat16(v.w);
    __nv_bfloat16 lx = __float2bfloat16(v.x - __bfloat162float(hx));
    __nv_bfloat16 ly = __float2bfloat16(v.y - __bfloat162float(hy));
    __nv_bfloat16 lz = __float2bfloat16(v.z - __bfloat162float(hz));
    __nv_bfloat16 lw = __float2bfloat16(v.w - __bfloat162float(hw));
    *reinterpret_cast<__nv_bfloat162*>(&shi[idx])     = __nv_bfloat162(hx, hy);
    *reinterpret_cast<__nv_bfloat162*>(&shi[idx + 2]) = __nv_bfloat162(hz, hw);
    *reinterpret_cast<__nv_bfloat162*>(&slo[idx])     = __nv_bfloat162(lx, ly);
    *reinterpret_cast<__nv_bfloat162*>(&slo[idx + 2]) = __nv_bfloat162(lz, lw);
}

// load A fragment (m16 x k16) from row-major [64][TSTR] bf16 tile
__device__ __forceinline__ void load_afrag(
    unsigned* a, const __nv_bfloat16* s, int mbase, int sk, int g, int t)
{
    const int r0 = (mbase + g) * TSTR + sk + 2 * t;
    const int r1 = (mbase + g + 8) * TSTR + sk + 2 * t;
    a[0] = *reinterpret_cast<const unsigned*>(&s[r0]);
    a[1] = *reinterpret_cast<const unsigned*>(&s[r1]);
    a[2] = *reinterpret_cast<const unsigned*>(&s[r0 + 8]);
    a[3] = *reinterpret_cast<const unsigned*>(&s[r1 + 8]);
}

// load B fragment (k16 x n8, col layout == W[n][k] row-major) from [64][TSTR]
__device__ __forceinline__ void load_bfrag(
    unsigned* b, const __nv_bfloat16* s, int nbase, int sk, int g, int t)
{
    const int r = (nbase + g) * TSTR + sk + 2 * t;
    b[0] = *reinterpret_cast<const unsigned*>(&s[r]);
    b[1] = *reinterpret_cast<const unsigned*>(&s[r + 8]);
}

// ---------------------------------------------------------------------------
// Fused quaternion-complex dense on tensor cores (bf16 split emulation):
//   outA[m,n] = Xa.Wa^T + j2 * Xb.Wb^T + ba[n]
//   outB[m,n] = Xa.Wb^T +      Xb.Wa^T + bb[n]
// Each fp32 GEMM emulated as hi*hi + hi*lo + lo*hi in bf16 (fp32 accum).
// 64x64 CTA tile, BK=32, 256 threads = 8 warps (4x2), warp tile 16x32.
// ---------------------------------------------------------------------------
__global__ __launch_bounds__(256) void qc_gemm_mma_kernel(
    const float* __restrict__ xa, const float* __restrict__ xb,
    const float* __restrict__ wa, const float* __restrict__ wb,
    const float* __restrict__ ba, const float* __restrict__ bb,
    const float* __restrict__ theta_ptr,
    float* __restrict__ outA, float* __restrict__ outB)
{
    __shared__ __nv_bfloat16 sXaH[64 * TSTR], sXaL[64 * TSTR];
    __shared__ __nv_bfloat16 sXbH[64 * TSTR], sXbL[64 * TSTR];
    __shared__ __nv_bfloat16 sWaH[64 * TSTR], sWaL[64 * TSTR];
    __shared__ __nv_bfloat16 sWbH[64 * TSTR], sWbL[64 * TSTR];

    const int tid = threadIdx.x;
    const int lane = tid & 31;
    const int wid = tid >> 5;
    const int warp_m = wid >> 1;          // 0..3 -> 16-row slab
    const int warp_n = wid & 1;           // 0..1 -> 32-col slab
    const int g = lane >> 2;              // 0..7
    const int t = lane & 3;               // 0..3

    const int m0 = blockIdx.y * 64;
    const int n0 = blockIdx.x * 64;

    const float j2 = sinf(2.0f * theta_ptr[0]) - 1.0f;

    // loader mapping: 2 chunks of 32 rows, float4 each
    const int lrow = tid >> 3;            // 0..31
    const int lcol = (tid & 7) << 2;      // 0,4,...,28

    float accA1[4][4] = {};   // Xa.Wa
    float accA2[4][4] = {};   // Xb.Wb
    float accB [4][4] = {};   // Xa.Wb + Xb.Wa

    for (int k0 = 0; k0 < EG; k0 += 32) {
        float4 vxa0 = *(const float4*)&xa[(m0 + lrow) * EG + k0 + lcol];
        float4 vxa1 = *(const float4*)&xa[(m0 + lrow + 32) * EG + k0 + lcol];
        float4 vxb0 = *(const float4*)&xb[(m0 + lrow) * EG + k0 + lcol];
        float4 vxb1 = *(const float4*)&xb[(m0 + lrow + 32) * EG + k0 + lcol];
        float4 vwa0 = *(const float4*)&wa[(n0 + lrow) * EG + k0 + lcol];
        float4 vwa1 = *(const float4*)&wa[(n0 + lrow + 32) * EG + k0 + lcol];
        float4 vwb0 = *(const float4*)&wb[(n0 + lrow) * EG + k0 + lcol];
        float4 vwb1 = *(const float4*)&wb[(n0 + lrow + 32) * EG + k0 + lcol];

        __syncthreads();   // previous iteration compute done before overwrite

        const int i0 = lrow * TSTR + lcol;
        const int i1 = (lrow + 32) * TSTR + lcol;
        split_store4(sXaH, sXaL, i0, vxa0);
        split_store4(sXaH, sXaL, i1, vxa1);
        split_store4(sXbH, sXbL, i0, vxb0);
        split_store4(sXbH, sXbL, i1, vxb1);
        split_store4(sWaH, sWaL, i0, vwa0);
        split_store4(sWaH, sWaL, i1, vwa1);
        split_store4(sWbH, sWbL, i0, vwb0);
        split_store4(sWbH, sWbL, i1, vwb1);

        __syncthreads();

        #pragma unroll
        for (int ks = 0; ks < 2; ks++) {
            const int sk = ks * 16;
            unsigned aXaH[4], aXaL[4], aXbH[4], aXbL[4];
            load_afrag(aXaH, sXaH, warp_m * 16, sk, g, t);
            load_afrag(aXaL, sXaL, warp_m * 16, sk, g, t);
            load_afrag(aXbH, sXbH, warp_m * 16, sk, g, t);
            load_afrag(aXbL, sXbL, warp_m * 16, sk, g, t);

            #pragma unroll
            for (int f = 0; f < 4; f++) {
                const int nbase = warp_n * 32 + f * 8;
                unsigned bWaH[2], bWaL[2], bWbH[2], bWbL[2];
                load_bfrag(bWaH, sWaH, nbase, sk, g, t);
                load_bfrag(bWaL, sWaL, nbase, sk, g, t);
                load_bfrag(bWbH, sWbH, nbase, sk, g, t);
                load_bfrag(bWbL, sWbL, nbase, sk, g, t);

                // A1 = Xa.Wa  (hi*hi + hi*lo + lo*hi)
                mma_bf16(accA1[f], aXaH, bWaH);
                mma_bf16(accA1[f], aXaH, bWaL);
                mma_bf16(accA1[f], aXaL, bWaH);
                // A2 = Xb.Wb
                mma_bf16(accA2[f], aXbH, bWbH);
                mma_bf16(accA2[f], aXbH, bWbL);
                mma_bf16(accA2[f], aXbL, bWbH);
                // B = Xa.Wb + Xb.Wa
                mma_bf16(accB[f], aXaH, bWbH);
                mma_bf16(accB[f], aXaH, bWbL);
                mma_bf16(accB[f], aXaL, bWbH);
                mma_bf16(accB[f], aXbH, bWaH);
                mma_bf16(accB[f], aXbH, bWaL);
                mma_bf16(accB[f], aXbL, bWaH);
            }
        }
    }

    // epilogue: D frag mapping c0=[g][2t], c1=[g][2t+1], c2=[g+8][2t], c3=[g+8][2t+1]
    #pragma unroll
    for (int f = 0; f < 4; f++) {
        const int n = n0 + warp_n * 32 + f * 8 + 2 * t;
        const int r0 = m0 + warp_m * 16 + g;
        const int r1 = r0 + 8;
        const float ba0 = ba[n], ba1 = ba[n + 1];
        const float bb0 = bb[n], bb1 = bb[n + 1];

        float2 oa0 = { accA1[f][0] + j2 * accA2[f][0] + ba0,
                       accA1[f][1] + j2 * accA2[f][1] + ba1 };
        float2 oa1 = { accA1[f][2] + j2 * accA2[f][2] + ba0,
                       accA1[f][3] + j2 * accA2[f][3] + ba1 };
        float2 ob0 = { accB[f][0] + bb0, accB[f][1] + bb1 };
        float2 ob1 = { accB[f][2] + bb0, accB[f][3] + bb1 };

        *(float2*)&outA[r0 * EG + n] = oa0;
        *(float2*)&outA[r1 * EG + n] = oa1;
        *(float2*)&outB[r0 * EG + n] = ob0;
        *(float2*)&outB[r1 * EG + n] = ob1;
    }
}

// ---------------------------------------------------------------------------
// RoPE applied in place to g_qa, g_qb, g_ka, g_kb (fp32 throughout!).
// ---------------------------------------------------------------------------
__global__ __launch_bounds__(256) void rope_kernel()
{
    const int PAIRS = MG * (EG / 2);          // per tensor: 2048 * 512
    int tt = blockIdx.x * blockDim.x + threadIdx.x;
    if (tt >= 4 * PAIRS) return;

    const int w = tt / PAIRS;
    const int p = tt % PAIRS;
    float* X = (w == 0) ? g_qa : (w == 1) ? g_qb : (w == 2) ? g_ka : g_kb;

    const int row = p >> 9;          // / 512
    const int pp  = p & 511;
    const int h   = pp >> 5;
    const int i   = pp & 31;
    const int s   = row & (SG - 1);  // row % S

    // freq = 10000^(-i/32) = exp2(-i * log2(10000)/32)
    const float freq = exp2f(-(float)i * (13.287712379549449f / 32.0f));
    float sn, cs;
    sincosf((float)s * freq, &sn, &cs);

    const int base = row * EG + h * DH + i;
    const float x1 = X[base];
    const float x2 = X[base + 32];
    X[base]      = x1 * cs - x2 * sn;
    X[base + 32] = x2 * cs + x1 * sn;
}

// ---------------------------------------------------------------------------
// Flash-style complex-magnitude attention (unchanged from R0 baseline).
// ---------------------------------------------------------------------------
__global__ __launch_bounds__(256) void attn_kernel(const float* __restrict__ thetas_head)
{
    __shared__ float sQa[32][65];
    __shared__ float sQb[32][65];
    __shared__ float sKa[32][65];   // reused for Va
    __shared__ float sKb[32][65];   // reused for Vb
    __shared__ float sP [32][33];

    const int b  = blockIdx.z;
    const int h  = blockIdx.y;
    const int r0 = blockIdx.x * 32;
    const int tid = threadIdx.x;
    const int row = tid >> 3;       // 0..31
    const int c   = tid & 7;        // 0..7

    const float j2h = sinf(2.0f * thetas_head[h]) - 1.0f;

    for (int idx = tid; idx < 32 * 64; idx += 256) {
        const int i = idx >> 6, d = idx & 63;
        const int g = (b * SG + r0 + i) * EG + h * DH + d;
        sQa[i][d] = g_qa[g];
        sQb[i][d] = g_qb[g];
    }

    float m = -1e30f, l = 0.0f;
    float acc_a[8] = {};
    float acc_b[8] = {};

    const int ntiles = (r0 >> 5) + 1;
    for (int t = 0; t < ntiles; t++) {
        const int k0 = t * 32;

        __syncthreads();
        for (int idx = tid; idx < 32 * 64; idx += 256) {
            const int i = idx >> 6, d = idx & 63;
            const int g = (b * SG + k0 + i) * EG + h * DH + d;
            sKa[i][d] = g_ka[g];
            sKb[i][d] = g_kb[g];
        }
        __syncthreads();

        float sa[4] = {}, sb[4] = {};
        for (int d = 0; d < 64; d++) {
            const float qaf = sQa[row][d];
            const float qbf = sQb[row][d];
            const float qbj = j2h * qbf;
            #pragma unroll
            for (int jj = 0; jj < 4; jj++) {
                const int j = c * 4 + jj;
                const float kaf = sKa[j][d];
                const float kbf = sKb[j][d];
                sa[jj] += qaf * kaf + qbj * kbf;
                sb[jj] += qaf * kbf + qbf * kaf;
            }
        }

        float mt = -1e30f;
        float mag[4];
        #pragma unroll
        for (int jj = 0; jj < 4; jj++) {
            const int kidx = k0 + c * 4 + jj;
            if (kidx <= r0 + row) {
                mag[jj] = sqrtf(sa[jj] * sa[jj] + sb[jj] * sb[jj] + 1e-8f) * 0.125f;
            } else {
                mag[jj] = -1e9f;
            }
            mt = fmaxf(mt, mag[jj]);
        }
        #pragma unroll
        for (int o = 1; o < 8; o <<= 1)
            mt = fmaxf(mt, __shfl_xor_sync(0xffffffffu, mt, o));

        const float mnew = fmaxf(m, mt);
        float p[4], psum = 0.0f;
        #pragma unroll
        for (int jj = 0; jj < 4; jj++) {
            p[jj] = expf(mag[jj] - mnew);
            psum += p[jj];
        }
        #pragma unroll
        for (int o = 1; o < 8; o <<= 1)
            psum += __shfl_xor_sync(0xffffffffu, psum, o);

        const float scale = expf(m - mnew);
        l = l * scale + psum;
        m = mnew;
        #pragma unroll
        for (int dd = 0; dd < 8; dd++) { acc_a[dd] *= scale; acc_b[dd] *= scale; }

        #pragma unroll
        for (int jj = 0; jj < 4; jj++) sP[row][c * 4 + jj] = p[jj];
        __syncthreads();

        for (int idx = tid; idx < 32 * 64; idx += 256) {
            const int i = idx >> 6, d = idx & 63;
            const int g = (b * SG + k0 + i) * EG + h * DH + d;
            sKa[i][d] = g_va[g];
            sKb[i][d] = g_vb[g];
        }
        __syncthreads();

        #pragma unroll 4
        for (int j = 0; j < 32; j++) {
            const float pv = sP[row][j];
            #pragma unroll
            for (int dd = 0; dd < 8; dd++) {
                acc_a[dd] += pv * sKa[j][c * 8 + dd];
                acc_b[dd] += pv * sKb[j][c * 8 + dd];
            }
        }
    }

    const float inv_l = 1.0f / l;
    const int g = (b * SG + r0 + row) * EG + h * DH + c * 8;
    #pragma unroll
    for (int dd = 0; dd < 8; dd++) {
        g_oa[g + dd] = acc_a[dd] * inv_l;
        g_ob[g + dd] = acc_b[dd] * inv_l;
    }
}

// ---------------------------------------------------------------------------
extern "C" void kernel_launch(void* const* d_in, const int* in_sizes, int n_in,
                              void* d_out, int out_size)
{
    const float* x_q_a  = (const float*)d_in[0];
    const float* x_q_b  = (const float*)d_in[1];
    const float* x_kv_a = (const float*)d_in[2];
    const float* x_kv_b = (const float*)d_in[3];
    // d_in[4] = mask (causal tril) -- encoded directly in the attention kernel
    const float* layer_theta = (const float*)d_in[5];
    const float* thetas_head = (const float*)d_in[6];
    const float* q_wa = (const float*)d_in[7];
    const float* q_wb = (const float*)d_in[8];
    const float* q_ba = (const float*)d_in[9];
    const float* q_bb = (const float*)d_in[10];
    const float* k_wa = (const float*)d_in[11];
    const float* k_wb = (const float*)d_in[12];
    const float* k_ba = (const float*)d_in[13];
    const float* k_bb = (const float*)d_in[14];
    const float* v_wa = (const float*)d_in[15];
    const float* v_wb = (const float*)d_in[16];
    const float* v_ba = (const float*)d_in[17];
    const float* v_bb = (const float*)d_in[18];
    const float* o_wa = (const float*)d_in[19];
    const float* o_wb = (const float*)d_in[20];
    const float* o_ba = (const float*)d_in[21];
    const float* o_bb = (const float*)d_in[22];

    float *qa, *qb, *ka, *kb, *va, *vb, *oa, *ob;
    cudaGetSymbolAddress((void**)&qa, g_qa);
    cudaGetSymbolAddress((void**)&qb, g_qb);
    cudaGetSymbolAddress((void**)&ka, g_ka);
    cudaGetSymbolAddress((void**)&kb, g_kb);
    cudaGetSymbolAddress((void**)&va, g_va);
    cudaGetSymbolAddress((void**)&vb, g_vb);
    cudaGetSymbolAddress((void**)&oa, g_oa);
    cudaGetSymbolAddress((void**)&ob, g_ob);

    float* outA = (float*)d_out;
    float* outB = (float*)d_out + (size_t)MG * EG;

    const dim3 gg(EG / 64, MG / 64);

    // q / k / v projections (tensor-core bf16-split)
    qc_gemm_mma_kernel<<<gg, 256>>>(x_q_a,  x_q_b,  q_wa, q_wb, q_ba, q_bb, layer_theta, qa, qb);
    qc_gemm_mma_kernel<<<gg, 256>>>(x_kv_a, x_kv_b, k_wa, k_wb, k_ba, k_bb, layer_theta, ka, kb);
    qc_gemm_mma_kernel<<<gg, 256>>>(x_kv_a, x_kv_b, v_wa, v_wb, v_ba, v_bb, layer_theta, va, vb);

    // RoPE on qa,qb,ka,kb (in place)
    rope_kernel<<<(4 * MG * (EG / 2)) / 256, 256>>>();

    // flash complex-magnitude attention -> g_oa, g_ob
    attn_kernel<<<dim3(SG / 32, HG, 2), 256>>>(thetas_head);

    // output projection straight into d_out (out_a then out_b)
    qc_gemm_mma_kernel<<<gg, 256>>>(oa, ob, o_wa, o_wb, o_ba, o_bb, layer_theta, outA, outB);
}

// round 5
// speedup vs baseline: 4.0078x; 1.9806x over previous
#include <cuda_runtime.h>
#include <cuda_bf16.h>
#include <math.h>

// Problem constants
#define EG 1024      // embed dim
#define MG 2048      // B*S rows
#define SG 1024      // seq len
#define HG 16        // heads
#define DH 64        // head dim

// ---------------- scratch (device globals: no runtime allocation allowed) ----
__device__ float g_qa[MG * EG];
__device__ float g_qb[MG * EG];
__device__ float g_ka[MG * EG];
__device__ float g_kb[MG * EG];
__device__ float g_va[MG * EG];
__device__ float g_vb[MG * EG];
__device__ float g_oa[MG * EG];
__device__ float g_ob[MG * EG];

// ---------------------------------------------------------------------------
// bf16 MMA helper: D += A(16x16,row) * B(16x8,col)   fp32 accum
// ---------------------------------------------------------------------------
__device__ __forceinline__ void mma_bf16(float* c, const unsigned* a, const unsigned* b)
{
    asm volatile(
        "mma.sync.aligned.m16n8k16.row.col.f32.bf16.bf16.f32 "
        "{%0,%1,%2,%3}, {%4,%5,%6,%7}, {%8,%9}, {%0,%1,%2,%3};"
        : "+f"(c[0]), "+f"(c[1]), "+f"(c[2]), "+f"(c[3])
        : "r"(a[0]), "r"(a[1]), "r"(a[2]), "r"(a[3]),
          "r"(b[0]), "r"(b[1]));
}

// pack two floats into bf16x2 (hi parts)
__device__ __forceinline__ unsigned pack_hi2(float x, float y)
{
    __nv_bfloat162 h(__float2bfloat16(x), __float2bfloat16(y));
    return *reinterpret_cast<unsigned*>(&h);
}
// pack the residuals (lo parts)
__device__ __forceinline__ unsigned pack_lo2(float x, float y)
{
    float hx = __bfloat162float(__float2bfloat16(x));
    float hy = __bfloat162float(__float2bfloat16(y));
    __nv_bfloat162 l(__float2bfloat16(x - hx), __float2bfloat16(y - hy));
    return *reinterpret_cast<unsigned*>(&l);
}

// smem tile strides (bf16 halfword units). BK=32 + pad 8 -> conflict-free frags.
#define TSTR 40

// split fp32 -> bf16 hi/lo, write pairs into smem tiles
__device__ __forceinline__ void split_store4(
    __nv_bfloat16* shi, __nv_bfloat16* slo, int idx, float4 v)
{
    __nv_bfloat16 hx = __float2bfloat16(v.x);
    __nv_bfloat16 hy = __float2bfloat16(v.y);
    __nv_bfloat16 hz = __float2bfloat16(v.z);
    __nv_bfloat16 hw = __float2bfloat16(v.w);
    __nv_bfloat16 lx = __float2bfloat16(v.x - __bfloat162float(hx));
    __nv_bfloat16 ly = __float2bfloat16(v.y - __bfloat162float(hy));
    __nv_bfloat16 lz = __float2bfloat16(v.z - __bfloat162float(hz));
    __nv_bfloat16 lw = __float2bfloat16(v.w - __bfloat162float(hw));
    *reinterpret_cast<__nv_bfloat162*>(&shi[idx])     = __nv_bfloat162(hx, hy);
    *reinterpret_cast<__nv_bfloat162*>(&shi[idx + 2]) = __nv_bfloat162(hz, hw);
    *reinterpret_cast<__nv_bfloat162*>(&slo[idx])     = __nv_bfloat162(lx, ly);
    *reinterpret_cast<__nv_bfloat162*>(&slo[idx + 2]) = __nv_bfloat162(lz, lw);
}

// load A fragment (m16 x k16) from row-major [64][TSTR] bf16 tile
__device__ __forceinline__ void load_afrag(
    unsigned* a, const __nv_bfloat16* s, int mbase, int sk, int g, int t)
{
    const int r0 = (mbase + g) * TSTR + sk + 2 * t;
    const int r1 = (mbase + g + 8) * TSTR + sk + 2 * t;
    a[0] = *reinterpret_cast<const unsigned*>(&s[r0]);
    a[1] = *reinterpret_cast<const unsigned*>(&s[r1]);
    a[2] = *reinterpret_cast<const unsigned*>(&s[r0 + 8]);
    a[3] = *reinterpret_cast<const unsigned*>(&s[r1 + 8]);
}

// load B fragment (k16 x n8, col layout == W[n][k] row-major) from [n][stride]
template<int STRIDE>
__device__ __forceinline__ void load_bfragS(
    unsigned* b, const __nv_bfloat16* s, int nbase, int sk, int g, int t)
{
    const int r = (nbase + g) * STRIDE + sk + 2 * t;
    b[0] = *reinterpret_cast<const unsigned*>(&s[r]);
    b[1] = *reinterpret_cast<const unsigned*>(&s[r + 8]);
}

// ---------------------------------------------------------------------------
// Fused quaternion-complex dense on tensor cores (bf16 split emulation).
// (unchanged from R3 -- validated at rel_err 3.4e-5)
// ---------------------------------------------------------------------------
__global__ __launch_bounds__(256) void qc_gemm_mma_kernel(
    const float* __restrict__ xa, const float* __restrict__ xb,
    const float* __restrict__ wa, const float* __restrict__ wb,
    const float* __restrict__ ba, const float* __restrict__ bb,
    const float* __restrict__ theta_ptr,
    float* __restrict__ outA, float* __restrict__ outB)
{
    __shared__ __nv_bfloat16 sXaH[64 * TSTR], sXaL[64 * TSTR];
    __shared__ __nv_bfloat16 sXbH[64 * TSTR], sXbL[64 * TSTR];
    __shared__ __nv_bfloat16 sWaH[64 * TSTR], sWaL[64 * TSTR];
    __shared__ __nv_bfloat16 sWbH[64 * TSTR], sWbL[64 * TSTR];

    const int tid = threadIdx.x;
    const int lane = tid & 31;
    const int wid = tid >> 5;
    const int warp_m = wid >> 1;
    const int warp_n = wid & 1;
    const int g = lane >> 2;
    const int t = lane & 3;

    const int m0 = blockIdx.y * 64;
    const int n0 = blockIdx.x * 64;

    const float j2 = sinf(2.0f * theta_ptr[0]) - 1.0f;

    const int lrow = tid >> 3;
    const int lcol = (tid & 7) << 2;

    float accA1[4][4] = {};
    float accA2[4][4] = {};
    float accB [4][4] = {};

    for (int k0 = 0; k0 < EG; k0 += 32) {
        float4 vxa0 = *(const float4*)&xa[(m0 + lrow) * EG + k0 + lcol];
        float4 vxa1 = *(const float4*)&xa[(m0 + lrow + 32) * EG + k0 + lcol];
        float4 vxb0 = *(const float4*)&xb[(m0 + lrow) * EG + k0 + lcol];
        float4 vxb1 = *(const float4*)&xb[(m0 + lrow + 32) * EG + k0 + lcol];
        float4 vwa0 = *(const float4*)&wa[(n0 + lrow) * EG + k0 + lcol];
        float4 vwa1 = *(const float4*)&wa[(n0 + lrow + 32) * EG + k0 + lcol];
        float4 vwb0 = *(const float4*)&wb[(n0 + lrow) * EG + k0 + lcol];
        float4 vwb1 = *(const float4*)&wb[(n0 + lrow + 32) * EG + k0 + lcol];

        __syncthreads();

        const int i0 = lrow * TSTR + lcol;
        const int i1 = (lrow + 32) * TSTR + lcol;
        split_store4(sXaH, sXaL, i0, vxa0);
        split_store4(sXaH, sXaL, i1, vxa1);
        split_store4(sXbH, sXbL, i0, vxb0);
        split_store4(sXbH, sXbL, i1, vxb1);
        split_store4(sWaH, sWaL, i0, vwa0);
        split_store4(sWaH, sWaL, i1, vwa1);
        split_store4(sWbH, sWbL, i0, vwb0);
        split_store4(sWbH, sWbL, i1, vwb1);

        __syncthreads();

        #pragma unroll
        for (int ks = 0; ks < 2; ks++) {
            const int sk = ks * 16;
            unsigned aXaH[4], aXaL[4], aXbH[4], aXbL[4];
            load_afrag(aXaH, sXaH, warp_m * 16, sk, g, t);
            load_afrag(aXaL, sXaL, warp_m * 16, sk, g, t);
            load_afrag(aXbH, sXbH, warp_m * 16, sk, g, t);
            load_afrag(aXbL, sXbL, warp_m * 16, sk, g, t);

            #pragma unroll
            for (int f = 0; f < 4; f++) {
                const int nbase = warp_n * 32 + f * 8;
                unsigned bWaH[2], bWaL[2], bWbH[2], bWbL[2];
                load_bfragS<TSTR>(bWaH, sWaH, nbase, sk, g, t);
                load_bfragS<TSTR>(bWaL, sWaL, nbase, sk, g, t);
                load_bfragS<TSTR>(bWbH, sWbH, nbase, sk, g, t);
                load_bfragS<TSTR>(bWbL, sWbL, nbase, sk, g, t);

                mma_bf16(accA1[f], aXaH, bWaH);
                mma_bf16(accA1[f], aXaH, bWaL);
                mma_bf16(accA1[f], aXaL, bWaH);
                mma_bf16(accA2[f], aXbH, bWbH);
                mma_bf16(accA2[f], aXbH, bWbL);
                mma_bf16(accA2[f], aXbL, bWbH);
                mma_bf16(accB[f], aXaH, bWbH);
                mma_bf16(accB[f], aXaH, bWbL);
                mma_bf16(accB[f], aXaL, bWbH);
                mma_bf16(accB[f], aXbH, bWaH);
                mma_bf16(accB[f], aXbH, bWaL);
                mma_bf16(accB[f], aXbL, bWaH);
            }
        }
    }

    #pragma unroll
    for (int f = 0; f < 4; f++) {
        const int n = n0 + warp_n * 32 + f * 8 + 2 * t;
        const int r0 = m0 + warp_m * 16 + g;
        const int r1 = r0 + 8;
        const float ba0 = ba[n], ba1 = ba[n + 1];
        const float bb0 = bb[n], bb1 = bb[n + 1];

        float2 oa0 = { accA1[f][0] + j2 * accA2[f][0] + ba0,
                       accA1[f][1] + j2 * accA2[f][1] + ba1 };
        float2 oa1 = { accA1[f][2] + j2 * accA2[f][2] + ba0,
                       accA1[f][3] + j2 * accA2[f][3] + ba1 };
        float2 ob0 = { accB[f][0] + bb0, accB[f][1] + bb1 };
        float2 ob1 = { accB[f][2] + bb0, accB[f][3] + bb1 };

        *(float2*)&outA[r0 * EG + n] = oa0;
        *(float2*)&outA[r1 * EG + n] = oa1;
        *(float2*)&outB[r0 * EG + n] = ob0;
        *(float2*)&outB[r1 * EG + n] = ob1;
    }
}

// ---------------------------------------------------------------------------
// RoPE applied in place to g_qa, g_qb, g_ka, g_kb (fp32 throughout).
// ---------------------------------------------------------------------------
__global__ __launch_bounds__(256) void rope_kernel()
{
    const int PAIRS = MG * (EG / 2);
    int tt = blockIdx.x * blockDim.x + threadIdx.x;
    if (tt >= 4 * PAIRS) return;

    const int w = tt / PAIRS;
    const int p = tt % PAIRS;
    float* X = (w == 0) ? g_qa : (w == 1) ? g_qb : (w == 2) ? g_ka : g_kb;

    const int row = p >> 9;
    const int pp  = p & 511;
    const int h   = pp >> 5;
    const int i   = pp & 31;
    const int s   = row & (SG - 1);

    const float freq = exp2f(-(float)i * (13.287712379549449f / 32.0f));
    float sn, cs;
    sincosf((float)s * freq, &sn, &cs);

    const int base = row * EG + h * DH + i;
    const float x1 = X[base];
    const float x2 = X[base + 32];
    X[base]      = x1 * cs - x2 * sn;
    X[base + 32] = x2 * cs + x1 * sn;
}

// ---------------------------------------------------------------------------
// Tensor-core flash attention with complex-magnitude scores, bf16 hi/lo split.
//   s_a = qa.ka + qb.(j2h*kb) ;  s_b = qa.kb + qb.ka
//   mag = sqrt(s_a^2+s_b^2+1e-8)/8 ; causal ; online softmax ; O = P@V (a,b).
// CTA: 128 q rows, 8 warps (16 rows each), Bc=32 key tile, grid (S/128, H, B).
// K stored [key][dim] (stride 72); V stored transposed [dim][key] (stride 40).
// ---------------------------------------------------------------------------
#define KSTR 72
#define VSTR 40

__global__ __launch_bounds__(256) void attn_mma_kernel(const float* __restrict__ thetas_head)
{
    __shared__ __nv_bfloat16 sKaH[32 * KSTR], sKaL[32 * KSTR];
    __shared__ __nv_bfloat16 sKbH[32 * KSTR], sKbL[32 * KSTR];
    __shared__ __nv_bfloat16 sKjH[32 * KSTR], sKjL[32 * KSTR];
    __shared__ __nv_bfloat16 sVaH[64 * VSTR], sVaL[64 * VSTR];
    __shared__ __nv_bfloat16 sVbH[64 * VSTR], sVbL[64 * VSTR];

    const int b   = blockIdx.z;
    const int h   = blockIdx.y;
    const int r0  = blockIdx.x * 128;
    const int tid = threadIdx.x;
    const int lane = tid & 31;
    const int wid  = tid >> 5;
    const int g = lane >> 2;
    const int t = lane & 3;

    const float j2h = sinf(2.0f * thetas_head[h]) - 1.0f;

    // --- build Q fragments in registers (4 k-steps x 4 regs x {a,b}x{h,l}) ---
    unsigned qaH[4][4], qaL[4][4], qbH[4][4], qbL[4][4];
    {
        const int row0 = r0 + wid * 16 + g;
        const int base0 = (b * SG + row0) * EG + h * DH;
        const int base1 = base0 + 8 * EG;     // row0 + 8
        #pragma unroll
        for (int ks = 0; ks < 4; ks++) {
            const int col = ks * 16 + 2 * t;
            float2 a0 = *(const float2*)&g_qa[base0 + col];
            float2 a1 = *(const float2*)&g_qa[base1 + col];
            float2 a2 = *(const float2*)&g_qa[base0 + col + 8];
            float2 a3 = *(const float2*)&g_qa[base1 + col + 8];
            qaH[ks][0] = pack_hi2(a0.x, a0.y); qaL[ks][0] = pack_lo2(a0.x, a0.y);
            qaH[ks][1] = pack_hi2(a1.x, a1.y); qaL[ks][1] = pack_lo2(a1.x, a1.y);
            qaH[ks][2] = pack_hi2(a2.x, a2.y); qaL[ks][2] = pack_lo2(a2.x, a2.y);
            qaH[ks][3] = pack_hi2(a3.x, a3.y); qaL[ks][3] = pack_lo2(a3.x, a3.y);
            float2 b0 = *(const float2*)&g_qb[base0 + col];
            float2 b1 = *(const float2*)&g_qb[base1 + col];
            float2 b2 = *(const float2*)&g_qb[base0 + col + 8];
            float2 b3 = *(const float2*)&g_qb[base1 + col + 8];
            qbH[ks][0] = pack_hi2(b0.x, b0.y); qbL[ks][0] = pack_lo2(b0.x, b0.y);
            qbH[ks][1] = pack_hi2(b1.x, b1.y); qbL[ks][1] = pack_lo2(b1.x, b1.y);
            qbH[ks][2] = pack_hi2(b2.x, b2.y); qbL[ks][2] = pack_lo2(b2.x, b2.y);
            qbH[ks][3] = pack_hi2(b3.x, b3.y); qbL[ks][3] = pack_lo2(b3.x, b3.y);
        }
    }

    float oa[8][4] = {};
    float ob[8][4] = {};
    float mrow0 = -1e30f, mrow1 = -1e30f;
    float lrow0 = 0.0f,   lrow1 = 0.0f;

    const int ntiles = (r0 >> 5) + 4;
    for (int tile = 0; tile < ntiles; tile++) {
        const int k0 = tile * 32;

        __syncthreads();   // previous tile's smem reads done

        // ---- load K (ka, kb -> also kbj = j2h*kb), split hi/lo ----
        #pragma unroll
        for (int it = 0; it < 2; it++) {
            const int idx = tid + it * 256;     // 0..511
            const int n  = idx >> 4;            // key 0..31
            const int d4 = (idx & 15) << 2;     // dim 0,4,..,60
            const int ga = (b * SG + k0 + n) * EG + h * DH + d4;
            float4 vka = *(const float4*)&g_ka[ga];
            float4 vkb = *(const float4*)&g_kb[ga];
            const int si = n * KSTR + d4;
            split_store4(sKaH, sKaL, si, vka);
            split_store4(sKbH, sKbL, si, vkb);
            float4 vkj = { j2h * vkb.x, j2h * vkb.y, j2h * vkb.z, j2h * vkb.w };
            split_store4(sKjH, sKjL, si, vkj);
        }
        // ---- load V transposed: sV[dim][key] ----
        #pragma unroll
        for (int it = 0; it < 2; it++) {
            const int idx = tid + it * 256;
            const int n  = idx >> 4;            // key 0..31
            const int d4 = (idx & 15) << 2;     // dim
            const int ga = (b * SG + k0 + n) * EG + h * DH + d4;
            float4 vva = *(const float4*)&g_va[ga];
            float4 vvb = *(const float4*)&g_vb[ga];
            const float va4[4] = { vva.x, vva.y, vva.z, vva.w };
            const float vb4[4] = { vvb.x, vvb.y, vvb.z, vvb.w };
            #pragma unroll
            for (int j = 0; j < 4; j++) {
                const int si = (d4 + j) * VSTR + n;
                __nv_bfloat16 hv = __float2bfloat16(va4[j]);
                sVaH[si] = hv;
                sVaL[si] = __float2bfloat16(va4[j] - __bfloat162float(hv));
                __nv_bfloat16 hw = __float2bfloat16(vb4[j]);
                sVbH[si] = hw;
                sVbL[si] = __float2bfloat16(vb4[j] - __bfloat162float(hw));
            }
        }
        __syncthreads();

        const int wrow = r0 + wid * 16;            // warp's first q row
        if (k0 > wrow + 15) continue;               // fully masked for this warp

        // ---- scores: sa, sb (16 rows x 32 cols per warp) ----
        float sa[4][4] = {};
        float sb[4][4] = {};
        #pragma unroll
        for (int ks = 0; ks < 4; ks++) {
            const int sk = ks * 16;
            #pragma unroll
            for (int nf = 0; nf < 4; nf++) {
                const int nb = nf * 8;
                unsigned kaH[2], kaL[2], kbH[2], kbL[2], kjH[2], kjL[2];
                load_bfragS<KSTR>(kaH, sKaH, nb, sk, g, t);
                load_bfragS<KSTR>(kaL, sKaL, nb, sk, g, t);
                load_bfragS<KSTR>(kbH, sKbH, nb, sk, g, t);
                load_bfragS<KSTR>(kbL, sKbL, nb, sk, g, t);
                load_bfragS<KSTR>(kjH, sKjH, nb, sk, g, t);
                load_bfragS<KSTR>(kjL, sKjL, nb, sk, g, t);

                // sa = qa.ka + qb.kbj
                mma_bf16(sa[nf], qaH[ks], kaH);
                mma_bf16(sa[nf], qaH[ks], kaL);
                mma_bf16(sa[nf], qaL[ks], kaH);
                mma_bf16(sa[nf], qbH[ks], kjH);
                mma_bf16(sa[nf], qbH[ks], kjL);
                mma_bf16(sa[nf], qbL[ks], kjH);
                // sb = qa.kb + qb.ka
                mma_bf16(sb[nf], qaH[ks], kbH);
                mma_bf16(sb[nf], qaH[ks], kbL);
                mma_bf16(sb[nf], qaL[ks], kbH);
                mma_bf16(sb[nf], qbH[ks], kaH);
                mma_bf16(sb[nf], qbH[ks], kaL);
                mma_bf16(sb[nf], qbL[ks], kaH);
            }
        }

        // ---- magnitude + causal mask (reuse sa[][] as mag/p storage) ----
        const bool full = (k0 + 31 <= wrow);       // whole tile unmasked for warp
        float mt0 = -1e30f, mt1 = -1e30f;
        #pragma unroll
        for (int nf = 0; nf < 4; nf++) {
            #pragma unroll
            for (int c = 0; c < 4; c++) {
                float v = sqrtf(sa[nf][c] * sa[nf][c] + sb[nf][c] * sb[nf][c] + 1e-8f) * 0.125f;
                if (!full) {
                    const int col = k0 + nf * 8 + 2 * t + (c & 1);
                    const int row = wrow + g + ((c & 2) ? 8 : 0);
                    if (col > row) v = -1e9f;
                }
                sa[nf][c] = v;
                if (c & 2) mt1 = fmaxf(mt1, v); else mt0 = fmaxf(mt0, v);
            }
        }
        mt0 = fmaxf(mt0, __shfl_xor_sync(0xffffffffu, mt0, 1));
        mt0 = fmaxf(mt0, __shfl_xor_sync(0xffffffffu, mt0, 2));
        mt1 = fmaxf(mt1, __shfl_xor_sync(0xffffffffu, mt1, 1));
        mt1 = fmaxf(mt1, __shfl_xor_sync(0xffffffffu, mt1, 2));

        const float mn0 = fmaxf(mrow0, mt0);
        const float mn1 = fmaxf(mrow1, mt1);

        float ps0 = 0.0f, ps1 = 0.0f;
        #pragma unroll
        for (int nf = 0; nf < 4; nf++) {
            #pragma unroll
            for (int c = 0; c < 4; c++) {
                const float p = __expf(sa[nf][c] - ((c & 2) ? mn1 : mn0));
                sa[nf][c] = p;
                if (c & 2) ps1 += p; else ps0 += p;
            }
        }
        ps0 += __shfl_xor_sync(0xffffffffu, ps0, 1);
        ps0 += __shfl_xor_sync(0xffffffffu, ps0, 2);
        ps1 += __shfl_xor_sync(0xffffffffu, ps1, 1);
        ps1 += __shfl_xor_sync(0xffffffffu, ps1, 2);

        const float sc0 = __expf(mrow0 - mn0);
        const float sc1 = __expf(mrow1 - mn1);
        lrow0 = lrow0 * sc0 + ps0;  mrow0 = mn0;
        lrow1 = lrow1 * sc1 + ps1;  mrow1 = mn1;
        #pragma unroll
        for (int nf = 0; nf < 8; nf++) {
            oa[nf][0] *= sc0; oa[nf][1] *= sc0; oa[nf][2] *= sc1; oa[nf][3] *= sc1;
            ob[nf][0] *= sc0; ob[nf][1] *= sc0; ob[nf][2] *= sc1; ob[nf][3] *= sc1;
        }

        // ---- P fragments (C-frag -> A-frag in registers), split hi/lo ----
        unsigned pH[2][4], pL[2][4];
        #pragma unroll
        for (int kc = 0; kc < 2; kc++) {
            const int f = 2 * kc;
            pH[kc][0] = pack_hi2(sa[f][0],     sa[f][1]);
            pL[kc][0] = pack_lo2(sa[f][0],     sa[f][1]);
            pH[kc][1] = pack_hi2(sa[f][2],     sa[f][3]);
            pL[kc][1] = pack_lo2(sa[f][2],     sa[f][3]);
            pH[kc][2] = pack_hi2(sa[f + 1][0], sa[f + 1][1]);
            pL[kc][2] = pack_lo2(sa[f + 1][0], sa[f + 1][1]);
            pH[kc][3] = pack_hi2(sa[f + 1][2], sa[f + 1][3]);
            pL[kc][3] = pack_lo2(sa[f + 1][2], sa[f + 1][3]);
        }

        // ---- O += P @ V  (a and b), 3-term split ----
        #pragma unroll
        for (int nf = 0; nf < 8; nf++) {
            const int nb = nf * 8;
            #pragma unroll
            for (int kc = 0; kc < 2; kc++) {
                const int sk = kc * 16;
                unsigned vaH[2], vaL[2], vbH[2], vbL[2];
                load_bfragS<VSTR>(vaH, sVaH, nb, sk, g, t);
                load_bfragS<VSTR>(vaL, sVaL, nb, sk, g, t);
                load_bfragS<VSTR>(vbH, sVbH, nb, sk, g, t);
                load_bfragS<VSTR>(vbL, sVbL, nb, sk, g, t);

                mma_bf16(oa[nf], pH[kc], vaH);
                mma_bf16(oa[nf], pL[kc], vaH);
                mma_bf16(oa[nf], pH[kc], vaL);
                mma_bf16(ob[nf], pH[kc], vbH);
                mma_bf16(ob[nf], pL[kc], vbH);
                mma_bf16(ob[nf], pH[kc], vbL);
            }
        }
    }

    // ---- epilogue ----
    const float inv0 = 1.0f / lrow0;
    const float inv1 = 1.0f / lrow1;
    const int row0 = r0 + wid * 16 + g;
    const int base0 = (b * SG + row0) * EG + h * DH;
    const int base1 = base0 + 8 * EG;
    #pragma unroll
    for (int nf = 0; nf < 8; nf++) {
        const int d = nf * 8 + 2 * t;
        float2 va0 = { oa[nf][0] * inv0, oa[nf][1] * inv0 };
        float2 va1 = { oa[nf][2] * inv1, oa[nf][3] * inv1 };
        float2 vb0 = { ob[nf][0] * inv0, ob[nf][1] * inv0 };
        float2 vb1 = { ob[nf][2] * inv1, ob[nf][3] * inv1 };
        *(float2*)&g_oa[base0 + d] = va0;
        *(float2*)&g_oa[base1 + d] = va1;
        *(float2*)&g_ob[base0 + d] = vb0;
        *(float2*)&g_ob[base1 + d] = vb1;
    }
}

// ---------------------------------------------------------------------------
extern "C" void kernel_launch(void* const* d_in, const int* in_sizes, int n_in,
                              void* d_out, int out_size)
{
    const float* x_q_a  = (const float*)d_in[0];
    const float* x_q_b  = (const float*)d_in[1];
    const float* x_kv_a = (const float*)d_in[2];
    const float* x_kv_b = (const float*)d_in[3];
    // d_in[4] = mask (causal tril) -- encoded directly in the attention kernel
    const float* layer_theta = (const float*)d_in[5];
    const float* thetas_head = (const float*)d_in[6];
    const float* q_wa = (const float*)d_in[7];
    const float* q_wb = (const float*)d_in[8];
    const float* q_ba = (const float*)d_in[9];
    const float* q_bb = (const float*)d_in[10];
    const float* k_wa = (const float*)d_in[11];
    const float* k_wb = (const float*)d_in[12];
    const float* k_ba = (const float*)d_in[13];
    const float* k_bb = (const float*)d_in[14];
    const float* v_wa = (const float*)d_in[15];
    const float* v_wb = (const float*)d_in[16];
    const float* v_ba = (const float*)d_in[17];
    const float* v_bb = (const float*)d_in[18];
    const float* o_wa = (const float*)d_in[19];
    const float* o_wb = (const float*)d_in[20];
    const float* o_ba = (const float*)d_in[21];
    const float* o_bb = (const float*)d_in[22];

    float *qa, *qb, *ka, *kb, *va, *vb, *oa, *ob;
    cudaGetSymbolAddress((void**)&qa, g_qa);
    cudaGetSymbolAddress((void**)&qb, g_qb);
    cudaGetSymbolAddress((void**)&ka, g_ka);
    cudaGetSymbolAddress((void**)&kb, g_kb);
    cudaGetSymbolAddress((void**)&va, g_va);
    cudaGetSymbolAddress((void**)&vb, g_vb);
    cudaGetSymbolAddress((void**)&oa, g_oa);
    cudaGetSymbolAddress((void**)&ob, g_ob);

    float* outA = (float*)d_out;
    float* outB = (float*)d_out + (size_t)MG * EG;

    const dim3 gg(EG / 64, MG / 64);

    // q / k / v projections (tensor-core bf16-split)
    qc_gemm_mma_kernel<<<gg, 256>>>(x_q_a,  x_q_b,  q_wa, q_wb, q_ba, q_bb, layer_theta, qa, qb);
    qc_gemm_mma_kernel<<<gg, 256>>>(x_kv_a, x_kv_b, k_wa, k_wb, k_ba, k_bb, layer_theta, ka, kb);
    qc_gemm_mma_kernel<<<gg, 256>>>(x_kv_a, x_kv_b, v_wa, v_wb, v_ba, v_bb, layer_theta, va, vb);

    // RoPE on qa,qb,ka,kb (in place)
    rope_kernel<<<(4 * MG * (EG / 2)) / 256, 256>>>();

    // tensor-core flash complex-magnitude attention -> g_oa, g_ob
    attn_mma_kernel<<<dim3(SG / 128, HG, 2), 256>>>(thetas_head);

    // output projection straight into d_out (out_a then out_b)
    qc_gemm_mma_kernel<<<gg, 256>>>(oa, ob, o_wa, o_wb, o_ba, o_bb, layer_theta, outA, outB);
}